// round 12
// baseline (speedup 1.0000x reference)
#include <cuda_runtime.h>
#include <cuda_fp16.h>
#include <cstdint>

#define WTH 256

// ---------------- filter constants (db4-style reconstruction filters) -------
#define LO0f ( 0.23037781330885523f)
#define LO1f ( 0.7148465705525415f)
#define LO2f ( 0.6308807679295904f)
#define LO3f (-0.02798376941698385f)
#define LO4f (-0.18703481171888114f)
#define LO5f ( 0.030841381835986965f)
#define LO6f ( 0.032883011666982945f)
#define LO7f (-0.010597401784997278f)
#define HI0f (-0.010597401784997278f)
#define HI1f (-0.032883011666982945f)
#define HI2f ( 0.030841381835986965f)
#define HI3f ( 0.18703481171888114f)
#define HI4f (-0.02798376941698385f)
#define HI5f (-0.6308807679295904f)
#define HI6f ( 0.7148465705525415f)
#define HI7f (-0.23037781330885523f)

__constant__ int c_NA[10]  = {4096, 2051, 1029, 518, 262, 134, 70, 38, 22, 14};
__constant__ int c_OFF[9]  = {0, 2051, 3080, 3598, 3860, 3994, 4064, 4102, 4124};

// ---------------- scratch (device globals; no runtime allocation) -----------
#define NSPLIT 18
__device__ __align__(128) __half g_A[2048UL * 32768UL];    // relu(feats), fp16
__device__ __align__(128) __half g_W[192UL * 32768UL];     // W0 padded, fp16
__device__ __align__(128) float  g_part[NSPLIT][2048 * 192];
__device__ __align__(128) float  g_h0[2048 * 192];         // reduced+relu'd L0

// ============================ PTX helpers ====================================
__device__ __forceinline__ uint32_t smem_u32(const void* p) {
    uint32_t a;
    asm("{ .reg .u64 t; cvta.to.shared.u64 t, %1; cvt.u32.u64 %0, t; }"
        : "=r"(a) : "l"(p));
    return a;
}
__device__ __forceinline__ void cp16(uint32_t dst, const void* src) {
    asm volatile("cp.async.cg.shared.global [%0], [%1], 16;"
                 :: "r"(dst), "l"(src) : "memory");
}
__device__ __forceinline__ void cp_commit() {
    asm volatile("cp.async.commit_group;" ::: "memory");
}
template <int N>
__device__ __forceinline__ void cp_wait() {
    asm volatile("cp.async.wait_group %0;" :: "n"(N) : "memory");
}
__device__ __forceinline__ void ldm4(uint32_t* r, uint32_t a) {
    asm volatile("ldmatrix.sync.aligned.m8n8.x4.shared.b16 {%0,%1,%2,%3}, [%4];"
                 : "=r"(r[0]), "=r"(r[1]), "=r"(r[2]), "=r"(r[3]) : "r"(a));
}
__device__ __forceinline__ void mma_f16(float* c, const uint32_t* a,
                                        const uint32_t* b) {
    asm volatile("mma.sync.aligned.m16n8k16.row.col.f32.f16.f16.f32 "
                 "{%0,%1,%2,%3}, {%4,%5,%6,%7}, {%8,%9}, {%0,%1,%2,%3};"
                 : "+f"(c[0]), "+f"(c[1]), "+f"(c[2]), "+f"(c[3])
                 : "r"(a[0]), "r"(a[1]), "r"(a[2]), "r"(a[3]),
                   "r"(b[0]), "r"(b[1]));
}

// ---------------- DWT stage: src[n] -> ca[m], cd[m] -------------------------
__device__ __forceinline__ void dwt_stage(const float* __restrict__ src, int n,
                                          float* __restrict__ ca,
                                          float* __restrict__ cd, int m)
{
    const float LO[8] = {LO0f, LO1f, LO2f, LO3f, LO4f, LO5f, LO6f, LO7f};
    const float HI[8] = {HI0f, HI1f, HI2f, HI3f, HI4f, HI5f, HI6f, HI7f};
    for (int k = threadIdx.x; k < m; k += WTH) {
        int base = 2 * k;
        float alo = 0.0f, ahi = 0.0f;
        if (base >= 6 && base <= n - 2) {
            const float* p = src + base - 6;
            #pragma unroll
            for (int t = 0; t < 8; ++t) {
                float v = p[t];
                alo = fmaf(v, LO[t], alo);
                ahi = fmaf(v, HI[t], ahi);
            }
        } else {
            #pragma unroll
            for (int t = 0; t < 8; ++t) {
                int idx = base + t;
                int e = (idx < 6) ? (5 - idx)
                                  : ((idx < n + 6) ? (idx - 6) : (2 * n + 5 - idx));
                float v = src[e];
                alo = fmaf(v, LO[t], alo);
                ahi = fmaf(v, HI[t], ahi);
            }
        }
        ca[k] = alo;
        cd[k] = ahi;
    }
}

// ---------------- IDWT stage (intermediate, fp32 smem out) ------------------
template <bool HAS_CA, bool HAS_CD>
__device__ __forceinline__ void idwt_stage(const float* __restrict__ ca,
                                           const float* __restrict__ cd,
                                           int n, float* __restrict__ out)
{
    int half = n - 3;
    for (int u = threadIdx.x; u < half; u += WTH) {
        float ev = 0.0f, od = 0.0f;
        if (HAS_CA) {
            float a0 = ca[u], a1 = ca[u + 1], a2 = ca[u + 2], a3 = ca[u + 3];
            ev = fmaf(a3, LO0f, fmaf(a2, LO2f, fmaf(a1, LO4f, a0 * LO6f)));
            od = fmaf(a3, LO1f, fmaf(a2, LO3f, fmaf(a1, LO5f, a0 * LO7f)));
        }
        if (HAS_CD) {
            float d0 = cd[u], d1 = cd[u + 1], d2 = cd[u + 2], d3 = cd[u + 3];
            ev = fmaf(d3, HI0f, fmaf(d2, HI2f, fmaf(d1, HI4f, fmaf(d0, HI6f, ev))));
            od = fmaf(d3, HI1f, fmaf(d2, HI3f, fmaf(d1, HI5f, fmaf(d0, HI7f, od))));
        }
        float2 o2; o2.x = ev; o2.y = od;
        *reinterpret_cast<float2*>(out + 2 * u) = o2;
    }
}

// ---------------- IDWT final: relu + fp16 store to gmem ---------------------
template <bool HAS_CD>
__device__ __forceinline__ void idwt_final(const float* __restrict__ ca,
                                           const float* __restrict__ cd, int n,
                                           __half* __restrict__ dst)
{
    int half = n - 3;
    for (int u = threadIdx.x; u < half; u += WTH) {
        float a0 = ca[u], a1 = ca[u + 1], a2 = ca[u + 2], a3 = ca[u + 3];
        float ev = fmaf(a3, LO0f, fmaf(a2, LO2f, fmaf(a1, LO4f, a0 * LO6f)));
        float od = fmaf(a3, LO1f, fmaf(a2, LO3f, fmaf(a1, LO5f, a0 * LO7f)));
        if (HAS_CD) {
            float d0 = cd[u], d1 = cd[u + 1], d2 = cd[u + 2], d3 = cd[u + 3];
            ev = fmaf(d3, HI0f, fmaf(d2, HI2f, fmaf(d1, HI4f, fmaf(d0, HI6f, ev))));
            od = fmaf(d3, HI1f, fmaf(d2, HI3f, fmaf(d1, HI5f, fmaf(d0, HI7f, od))));
        }
        ev = fmaxf(ev, 0.0f);
        od = fmaxf(od, 0.0f);
        *reinterpret_cast<__half2*>(dst + 2 * u) = __floats2half2_rn(ev, od);
    }
}

// ---------------- kernel 1: per-row wavelet features (all in smem) ----------
extern "C" __global__ void __launch_bounds__(WTH)
wavelet_kernel(const float* __restrict__ x, int row_base)
{
    __shared__ __align__(16) float s_cds[4138];
    __shared__ __align__(16) float bufX[4096];
    __shared__ __align__(16) float bufB[2052];

    int row = row_base + blockIdx.x;
    const float* xr = x + (size_t)row * 4096;
    __half* hr = g_A + (size_t)row * 32768;

    for (int i = threadIdx.x; i < 4096; i += WTH) bufX[i] = xr[i];
    __syncthreads();

    {
        float* a_src = bufX;
        float* a_dst = bufB;
        #pragma unroll 1
        for (int l = 1; l <= 9; ++l) {
            dwt_stage(a_src, c_NA[l - 1], a_dst, s_cds + c_OFF[l - 1], c_NA[l]);
            __syncthreads();
            float* t = a_src; a_src = a_dst; a_dst = t;
        }
    }

    #pragma unroll 1
    for (int level = 2; level <= 9; ++level) {
        float* ping = bufX;
        float* pong = bufB;
        idwt_stage<false, true>(nullptr, s_cds + c_OFF[level - 1], c_NA[level], ping);
        __syncthreads();
        if (level == 2) {
            idwt_final<true>(ping, s_cds + c_OFF[0], c_NA[1], hr);
        } else {
            idwt_stage<true, true>(ping, s_cds + c_OFF[level - 2], c_NA[level - 1], pong);
            __syncthreads();
            { float* t = ping; ping = pong; pong = t; }
            for (int j = level - 3; j >= 1; --j) {
                idwt_stage<true, false>(ping, nullptr, c_NA[j + 1], pong);
                __syncthreads();
                float* t = ping; ping = pong; pong = t;
            }
            idwt_final<false>(ping, nullptr, c_NA[1],
                              hr + (size_t)(level - 2) * 4096);
        }
        __syncthreads();
    }
}

// ---------------- kernel 1b: W0 -> fp16 (padded to 192 rows) ----------------
extern "C" __global__ void __launch_bounds__(256)
wconv_kernel(const float* __restrict__ W0)
{
    int i = blockIdx.x * 256 + threadIdx.x;   // over 192*32768 elements
    int row = i >> 15;
    int col = i & 32767;
    float v = (row < 181) ? W0[(size_t)row * 32768 + col] : 0.0f;
    g_W[i] = __float2half_rn(v);
}

// ---------------- kernel 2: HMMA fp16 single-product split-K GEMM -----------
// CTA tile: 128(M) x 192(N) full-N; BK = 32 halves; 3-stage cp.async pipeline.
// smem per stage: A(128x80B=10240) + W(192x80B=15360) = 25600 B
// padded row stride: 40 halves = 80 B (conflict-free ldmatrix)
#define STAGE_B   25600
#define NSTAGE    3
#define GEMM_SMEM (NSTAGE * STAGE_B)
#define KSTEPS_TOT 1024          // 32768 / 32
#define SB_STEPS   57            // ceil(1024/18)

__device__ __forceinline__ void stage_load(uint32_t sbase, int m0, int kstep, int tid)
{
    size_t kb = (size_t)kstep * 64;           // byte offset along k
    #pragma unroll
    for (int j = 0; j < 5; ++j) {             // 1280 16B chunks / 256 threads
        int c = tid + j * 256;
        uint32_t dst;
        const char* src;
        if (c < 512) {                         // A tile: 128 rows x 4 chunks
            int row = c >> 2, kc = c & 3;
            dst = sbase + row * 80 + kc * 16;
            src = (const char*)g_A + ((size_t)(m0 + row) << 16) + kb + kc * 16;
        } else {                               // W tile: 192 rows x 4 chunks
            int rc = c - 512;
            int row = rc >> 2, kc = rc & 3;
            dst = sbase + 10240 + row * 80 + kc * 16;
            src = (const char*)g_W + ((size_t)row << 16) + kb + kc * 16;
        }
        cp16(dst, src);
    }
    cp_commit();
}

extern "C" __global__ void __launch_bounds__(256, 1)
gemm_hmma_kernel(int m_base)
{
    extern __shared__ __align__(128) char smem[];
    uint32_t sbase = smem_u32(smem);
    int tid = threadIdx.x;
    int wid = tid >> 5;
    int l   = tid & 31;
    int wm  = wid >> 2;     // 0..1 : 64 rows each
    int wn  = wid & 3;      // 0..3 : 48 cols each
    int m0  = m_base + blockIdx.x * 128;
    int sb  = blockIdx.y;
    int start = sb * SB_STEPS;
    int nst = KSTEPS_TOT - start;
    if (nst > SB_STEPS) nst = SB_STEPS;

    float acc[4][6][4] = {};

    stage_load(sbase,           m0, start,     tid);
    stage_load(sbase + STAGE_B, m0, start + 1, tid);

    uint32_t aoff = (uint32_t)((wm * 64 + (l & 15)) * 80 + (l >> 4) * 16);
    uint32_t boff = (uint32_t)(10240 +
                    (wn * 48 + (l & 7) + ((l >> 4) & 1) * 8) * 80 +
                    ((l >> 3) & 1) * 16);

    int st = 0;
    #pragma unroll 1
    for (int it = 0; it < nst; ++it) {
        if (it == nst - 1) cp_wait<0>(); else cp_wait<1>();
        __syncthreads();
        uint32_t buf = sbase + (uint32_t)st * STAGE_B;
        if (it + 2 < nst) {
            int st2 = st + 2; if (st2 >= 3) st2 -= 3;
            stage_load(sbase + (uint32_t)st2 * STAGE_B, m0, start + it + 2, tid);
        }

        #pragma unroll
        for (int ks = 0; ks < 2; ++ks) {
            uint32_t A[4][4], B[3][4];
            #pragma unroll
            for (int mi = 0; mi < 4; ++mi)
                ldm4(A[mi], buf + aoff + mi * (16 * 80) + ks * 32);
            #pragma unroll
            for (int nj = 0; nj < 3; ++nj)
                ldm4(B[nj], buf + boff + nj * (16 * 80) + ks * 32);
            #pragma unroll
            for (int mi = 0; mi < 4; ++mi)
                #pragma unroll
                for (int nj = 0; nj < 3; ++nj)
                    #pragma unroll
                    for (int h = 0; h < 2; ++h)
                        mma_f16(acc[mi][nj * 2 + h], A[mi], &B[nj][h * 2]);
        }
        ++st; if (st == 3) st = 0;
    }

    // epilogue: direct partial store
    float* outp = g_part[sb];
    #pragma unroll
    for (int mi = 0; mi < 4; ++mi) {
        int r0 = m0 + wm * 64 + mi * 16 + (l >> 2);
        #pragma unroll
        for (int n = 0; n < 6; ++n) {
            int col = wn * 48 + n * 8 + (l & 3) * 2;
            float2 v0, v1;
            v0.x = acc[mi][n][0]; v0.y = acc[mi][n][1];
            v1.x = acc[mi][n][2]; v1.y = acc[mi][n][3];
            *reinterpret_cast<float2*>(outp + (size_t)r0 * 192 + col) = v0;
            *reinterpret_cast<float2*>(outp + (size_t)(r0 + 8) * 192 + col) = v1;
        }
    }
}

// ---------------- kernel 3a: reduce partials + bias + relu ------------------
extern "C" __global__ void __launch_bounds__(256)
reduce_kernel(const float* __restrict__ b0)
{
    int i = blockIdx.x * 256 + threadIdx.x;   // over 2048*192
    int col = i % 192;
    float v = (col < 181) ? b0[col] : 0.0f;
    #pragma unroll
    for (int s = 0; s < NSPLIT; ++s) v += g_part[s][i];
    g_h0[i] = fmaxf(v, 0.0f);
}

// ---------------- kernel 3b: tiny MLP, 16 rows per block --------------------
#define MROWS 16
extern "C" __global__ void __launch_bounds__(256)
mlp_kernel(const float* __restrict__ W1, const float* __restrict__ b1,
           const float* __restrict__ W2, const float* __restrict__ b2,
           float* __restrict__ out)
{
    __shared__ float sW1[13 * 181];
    __shared__ float sW2[10 * 13];
    __shared__ float sb1[13], sb2[10];
    __shared__ float sc[MROWS][184];
    __shared__ float sh[MROWS][16];

    int tid = threadIdx.x;
    int row0 = blockIdx.x * MROWS;

    for (int i = tid; i < 13 * 181; i += 256) sW1[i] = W1[i];
    if (tid < 130) sW2[tid] = W2[tid];
    if (tid < 13) sb1[tid] = b1[tid];
    if (tid < 10) sb2[tid] = b2[tid];

    for (int i = tid; i < MROWS * 192; i += 256) {
        int r = i / 192, c = i % 192;
        float v = g_h0[(size_t)(row0 + r) * 192 + c];
        if (c < 181) sc[r][c] = v;
    }
    __syncthreads();

    if (tid < MROWS * 13) {
        int r = tid / 13, o = tid % 13;
        float v = sb1[o];
        const float* w = sW1 + o * 181;
        #pragma unroll 4
        for (int j = 0; j < 181; ++j) v = fmaf(sc[r][j], w[j], v);
        sh[r][o] = fmaxf(v, 0.0f);
    }
    __syncthreads();

    if (tid < MROWS * 10) {
        int r = tid / 10, o = tid % 10;
        float v = sb2[o];
        #pragma unroll
        for (int i = 0; i < 13; ++i) v = fmaf(sh[r][i], sW2[o * 13 + i], v);
        out[(size_t)(row0 + r) * 10 + o] = v;
    }
}

// ---------------- launcher: forked-stream pipelined graph -------------------
#define NCHUNK 4
#define CROWS  (2048 / NCHUNK)

extern "C" void kernel_launch(void* const* d_in, const int* in_sizes, int n_in,
                              void* d_out, int out_size)
{
    const float* x1 = (const float*)d_in[0];
    const float* W0 = (const float*)d_in[3];
    const float* b0 = (const float*)d_in[4];
    const float* W1 = (const float*)d_in[5];
    const float* b1 = (const float*)d_in[6];
    const float* W2 = (const float*)d_in[7];
    const float* b2 = (const float*)d_in[8];
    float* out = (float*)d_out;

    static int inited = 0;
    static cudaStream_t sW, sG;
    static cudaEvent_t eFork, eWC, eW[NCHUNK], eG;
    if (!inited) {
        cudaFuncSetAttribute(gemm_hmma_kernel,
                             cudaFuncAttributeMaxDynamicSharedMemorySize,
                             GEMM_SMEM);
        cudaStreamCreateWithFlags(&sW, cudaStreamNonBlocking);
        cudaStreamCreateWithFlags(&sG, cudaStreamNonBlocking);
        cudaEventCreateWithFlags(&eFork, cudaEventDisableTiming);
        cudaEventCreateWithFlags(&eWC,   cudaEventDisableTiming);
        cudaEventCreateWithFlags(&eG,    cudaEventDisableTiming);
        for (int c = 0; c < NCHUNK; ++c)
            cudaEventCreateWithFlags(&eW[c], cudaEventDisableTiming);
        inited = 1;
    }

    // fork: wconv runs concurrently with the first wavelet chunk
    cudaEventRecord(eFork, 0);
    cudaStreamWaitEvent(sW, eFork, 0);
    wconv_kernel<<<192 * 32768 / 256, 256, 0, sW>>>(W0);
    cudaEventRecord(eWC, sW);
    cudaStreamWaitEvent(sG, eWC, 0);        // all gemms need g_W

    // pipelined wavelet chunks -> gemm chunks
    for (int c = 0; c < NCHUNK; ++c) {
        wavelet_kernel<<<CROWS, WTH>>>(x1, c * CROWS);
        cudaEventRecord(eW[c], 0);
        cudaStreamWaitEvent(sG, eW[c], 0);
        dim3 gg(CROWS / 128, NSPLIT);       // 4 x 18 = 72 CTAs per chunk
        gemm_hmma_kernel<<<gg, 256, GEMM_SMEM, sG>>>(c * CROWS);
    }

    // join and finish on the origin stream
    cudaEventRecord(eG, sG);
    cudaStreamWaitEvent(0, eG, 0);
    reduce_kernel<<<2048 * 192 / 256, 256>>>(b0);
    mlp_kernel<<<2048 / MROWS, 256>>>(W1, b1, W2, b2, out);
}

// round 13
// speedup vs baseline: 1.5413x; 1.5413x over previous
#include <cuda_runtime.h>
#include <cuda_fp16.h>
#include <cstdint>

#define WTH 256

// ---------------- filter constants (db4-style reconstruction filters) -------
#define LO0f ( 0.23037781330885523f)
#define LO1f ( 0.7148465705525415f)
#define LO2f ( 0.6308807679295904f)
#define LO3f (-0.02798376941698385f)
#define LO4f (-0.18703481171888114f)
#define LO5f ( 0.030841381835986965f)
#define LO6f ( 0.032883011666982945f)
#define LO7f (-0.010597401784997278f)
#define HI0f (-0.010597401784997278f)
#define HI1f (-0.032883011666982945f)
#define HI2f ( 0.030841381835986965f)
#define HI3f ( 0.18703481171888114f)
#define HI4f (-0.02798376941698385f)
#define HI5f (-0.6308807679295904f)
#define HI6f ( 0.7148465705525415f)
#define HI7f (-0.23037781330885523f)

__constant__ int c_NA[10]  = {4096, 2051, 1029, 518, 262, 134, 70, 38, 22, 14};
__constant__ int c_OFF[9]  = {0, 2051, 3080, 3598, 3860, 3994, 4064, 4102, 4124};

// ---------------- scratch (device globals; no runtime allocation) -----------
#define NSPLIT 9
__device__ __align__(128) __half g_A[2048UL * 32768UL];    // relu(feats), fp16
__device__ __align__(128) __half g_W[192UL * 32768UL];     // W0 padded, fp16
__device__ __align__(128) float  g_part[NSPLIT][2048 * 192];

// ============================ PTX helpers ====================================
__device__ __forceinline__ uint32_t smem_u32(const void* p) {
    uint32_t a;
    asm("{ .reg .u64 t; cvta.to.shared.u64 t, %1; cvt.u32.u64 %0, t; }"
        : "=r"(a) : "l"(p));
    return a;
}
__device__ __forceinline__ void cp16(uint32_t dst, const void* src) {
    asm volatile("cp.async.cg.shared.global [%0], [%1], 16;"
                 :: "r"(dst), "l"(src) : "memory");
}
__device__ __forceinline__ void cp_commit() {
    asm volatile("cp.async.commit_group;" ::: "memory");
}
template <int N>
__device__ __forceinline__ void cp_wait() {
    asm volatile("cp.async.wait_group %0;" :: "n"(N) : "memory");
}
__device__ __forceinline__ void ldm4(uint32_t* r, uint32_t a) {
    asm volatile("ldmatrix.sync.aligned.m8n8.x4.shared.b16 {%0,%1,%2,%3}, [%4];"
                 : "=r"(r[0]), "=r"(r[1]), "=r"(r[2]), "=r"(r[3]) : "r"(a));
}
__device__ __forceinline__ void mma_f16(float* c, const uint32_t* a,
                                        const uint32_t* b) {
    asm volatile("mma.sync.aligned.m16n8k16.row.col.f32.f16.f16.f32 "
                 "{%0,%1,%2,%3}, {%4,%5,%6,%7}, {%8,%9}, {%0,%1,%2,%3};"
                 : "+f"(c[0]), "+f"(c[1]), "+f"(c[2]), "+f"(c[3])
                 : "r"(a[0]), "r"(a[1]), "r"(a[2]), "r"(a[3]),
                   "r"(b[0]), "r"(b[1]));
}

// ---------------- DWT stage: src[n] -> ca[m], cd[m] -------------------------
// src may live in global (level 1) or shared memory (generic pointer).
__device__ __forceinline__ void dwt_stage(const float* __restrict__ src, int n,
                                          float* __restrict__ ca,
                                          float* __restrict__ cd, int m)
{
    const float LO[8] = {LO0f, LO1f, LO2f, LO3f, LO4f, LO5f, LO6f, LO7f};
    const float HI[8] = {HI0f, HI1f, HI2f, HI3f, HI4f, HI5f, HI6f, HI7f};
    for (int k = threadIdx.x; k < m; k += WTH) {
        int base = 2 * k;
        float alo = 0.0f, ahi = 0.0f;
        if (base >= 6 && base <= n - 2) {
            const float* p = src + base - 6;
            #pragma unroll
            for (int t = 0; t < 8; ++t) {
                float v = p[t];
                alo = fmaf(v, LO[t], alo);
                ahi = fmaf(v, HI[t], ahi);
            }
        } else {
            #pragma unroll
            for (int t = 0; t < 8; ++t) {
                int idx = base + t;
                int e = (idx < 6) ? (5 - idx)
                                  : ((idx < n + 6) ? (idx - 6) : (2 * n + 5 - idx));
                float v = src[e];
                alo = fmaf(v, LO[t], alo);
                ahi = fmaf(v, HI[t], ahi);
            }
        }
        ca[k] = alo;
        cd[k] = ahi;
    }
}

// ---------------- IDWT stage (intermediate, fp32 smem out) ------------------
template <bool HAS_CA, bool HAS_CD>
__device__ __forceinline__ void idwt_stage(const float* __restrict__ ca,
                                           const float* __restrict__ cd,
                                           int n, float* __restrict__ out)
{
    int half = n - 3;
    for (int u = threadIdx.x; u < half; u += WTH) {
        float ev = 0.0f, od = 0.0f;
        if (HAS_CA) {
            float a0 = ca[u], a1 = ca[u + 1], a2 = ca[u + 2], a3 = ca[u + 3];
            ev = fmaf(a3, LO0f, fmaf(a2, LO2f, fmaf(a1, LO4f, a0 * LO6f)));
            od = fmaf(a3, LO1f, fmaf(a2, LO3f, fmaf(a1, LO5f, a0 * LO7f)));
        }
        if (HAS_CD) {
            float d0 = cd[u], d1 = cd[u + 1], d2 = cd[u + 2], d3 = cd[u + 3];
            ev = fmaf(d3, HI0f, fmaf(d2, HI2f, fmaf(d1, HI4f, fmaf(d0, HI6f, ev))));
            od = fmaf(d3, HI1f, fmaf(d2, HI3f, fmaf(d1, HI5f, fmaf(d0, HI7f, od))));
        }
        float2 o2; o2.x = ev; o2.y = od;
        *reinterpret_cast<float2*>(out + 2 * u) = o2;
    }
}

// ---------------- IDWT final: relu + fp16 store to gmem ---------------------
template <bool HAS_CD>
__device__ __forceinline__ void idwt_final(const float* __restrict__ ca,
                                           const float* __restrict__ cd, int n,
                                           __half* __restrict__ dst)
{
    int half = n - 3;
    for (int u = threadIdx.x; u < half; u += WTH) {
        float a0 = ca[u], a1 = ca[u + 1], a2 = ca[u + 2], a3 = ca[u + 3];
        float ev = fmaf(a3, LO0f, fmaf(a2, LO2f, fmaf(a1, LO4f, a0 * LO6f)));
        float od = fmaf(a3, LO1f, fmaf(a2, LO3f, fmaf(a1, LO5f, a0 * LO7f)));
        if (HAS_CD) {
            float d0 = cd[u], d1 = cd[u + 1], d2 = cd[u + 2], d3 = cd[u + 3];
            ev = fmaf(d3, HI0f, fmaf(d2, HI2f, fmaf(d1, HI4f, fmaf(d0, HI6f, ev))));
            od = fmaf(d3, HI1f, fmaf(d2, HI3f, fmaf(d1, HI5f, fmaf(d0, HI7f, od))));
        }
        ev = fmaxf(ev, 0.0f);
        od = fmaxf(od, 0.0f);
        *reinterpret_cast<__half2*>(dst + 2 * u) = __floats2half2_rn(ev, od);
    }
}

// ---------------- kernel 1: per-row wavelet features ------------------------
// Level-1 DWT reads x directly from gmem; recon intermediates fit in 2052 fl.
// smem = (4138 + 2052 + 2052)*4 = 32968 B  ->  6 CTAs/SM.
extern "C" __global__ void __launch_bounds__(WTH, 6)
wavelet_kernel(const float* __restrict__ x)
{
    __shared__ __align__(16) float s_cds[4138];
    __shared__ __align__(16) float bufA[2052];
    __shared__ __align__(16) float bufB[2052];

    int row = blockIdx.x;
    const float* xr = x + (size_t)row * 4096;
    __half* hr = g_A + (size_t)row * 32768;

    // ---- analysis: level 1 from gmem, levels 2..9 in smem ----
    dwt_stage(xr, 4096, bufA, s_cds + c_OFF[0], c_NA[1]);
    __syncthreads();
    {
        float* a_src = bufA;
        float* a_dst = bufB;
        #pragma unroll 1
        for (int l = 2; l <= 9; ++l) {
            dwt_stage(a_src, c_NA[l - 1], a_dst, s_cds + c_OFF[l - 1], c_NA[l]);
            __syncthreads();
            float* t = a_src; a_src = a_dst; a_dst = t;
        }
    }

    // ---- reconstructions for levels 2..9 ----
    #pragma unroll 1
    for (int level = 2; level <= 9; ++level) {
        float* ping = bufA;
        float* pong = bufB;
        idwt_stage<false, true>(nullptr, s_cds + c_OFF[level - 1], c_NA[level], ping);
        __syncthreads();
        if (level == 2) {
            idwt_final<true>(ping, s_cds + c_OFF[0], c_NA[1], hr);
        } else {
            idwt_stage<true, true>(ping, s_cds + c_OFF[level - 2], c_NA[level - 1], pong);
            __syncthreads();
            { float* t = ping; ping = pong; pong = t; }
            for (int j = level - 3; j >= 1; --j) {
                idwt_stage<true, false>(ping, nullptr, c_NA[j + 1], pong);
                __syncthreads();
                float* t = ping; ping = pong; pong = t;
            }
            idwt_final<false>(ping, nullptr, c_NA[1],
                              hr + (size_t)(level - 2) * 4096);
        }
        __syncthreads();
    }
}

// ---------------- kernel 1b: W0 -> fp16 (padded to 192 rows), vectorized ----
extern "C" __global__ void __launch_bounds__(256)
wconv_kernel(const float* __restrict__ W0)
{
    int i4 = (blockIdx.x * 256 + threadIdx.x) * 4;   // over 192*32768
    int row = i4 >> 15;
    __half2 h01, h23;
    if (row < 181) {
        int col = i4 & 32767;
        float4 v = *reinterpret_cast<const float4*>(
            W0 + (size_t)row * 32768 + col);
        h01 = __floats2half2_rn(v.x, v.y);
        h23 = __floats2half2_rn(v.z, v.w);
    } else {
        h01 = __floats2half2_rn(0.f, 0.f);
        h23 = h01;
    }
    __half2* dst = reinterpret_cast<__half2*>(g_W + i4);
    dst[0] = h01;
    dst[1] = h23;
}

// ---------------- kernel 2: HMMA fp16 single-product split-K GEMM -----------
// CTA tile: 128(M) x 192(N) full-N; BK = 32 halves; 4-stage cp.async pipeline.
#define STAGE_B   25600
#define NSTAGE    4
#define GEMM_SMEM (NSTAGE * STAGE_B)
#define KSTEPS_TOT 1024          // 32768 / 32
#define SB_STEPS   114           // ceil(1024/9)

__device__ __forceinline__ void stage_load(uint32_t sbase, int m0, int kstep, int tid)
{
    size_t kb = (size_t)kstep * 64;           // byte offset along k
    #pragma unroll
    for (int j = 0; j < 5; ++j) {             // 1280 16B chunks / 256 threads
        int c = tid + j * 256;
        uint32_t dst;
        const char* src;
        if (c < 512) {                         // A tile: 128 rows x 4 chunks
            int row = c >> 2, kc = c & 3;
            dst = sbase + row * 80 + kc * 16;
            src = (const char*)g_A + ((size_t)(m0 + row) << 16) + kb + kc * 16;
        } else {                               // W tile: 192 rows x 4 chunks
            int rc = c - 512;
            int row = rc >> 2, kc = rc & 3;
            dst = sbase + 10240 + row * 80 + kc * 16;
            src = (const char*)g_W + ((size_t)row << 16) + kb + kc * 16;
        }
        cp16(dst, src);
    }
    cp_commit();
}

extern "C" __global__ void __launch_bounds__(256, 1)
gemm_hmma_kernel()
{
    extern __shared__ __align__(128) char smem[];
    uint32_t sbase = smem_u32(smem);
    int tid = threadIdx.x;
    int wid = tid >> 5;
    int l   = tid & 31;
    int wm  = wid >> 2;     // 0..1 : 64 rows each
    int wn  = wid & 3;      // 0..3 : 48 cols each
    int m0  = blockIdx.x * 128;
    int sb  = blockIdx.y;
    int start = sb * SB_STEPS;
    int nst = KSTEPS_TOT - start;
    if (nst > SB_STEPS) nst = SB_STEPS;

    float acc[4][6][4] = {};

    stage_load(sbase,               m0, start,     tid);
    stage_load(sbase + STAGE_B,     m0, start + 1, tid);
    stage_load(sbase + 2 * STAGE_B, m0, start + 2, tid);

    uint32_t aoff = (uint32_t)((wm * 64 + (l & 15)) * 80 + (l >> 4) * 16);
    uint32_t boff = (uint32_t)(10240 +
                    (wn * 48 + (l & 7) + ((l >> 4) & 1) * 8) * 80 +
                    ((l >> 3) & 1) * 16);

    #pragma unroll 1
    for (int it = 0; it < nst; ++it) {
        if (it >= nst - 3) cp_wait<0>(); else cp_wait<2>();
        __syncthreads();
        uint32_t buf = sbase + (uint32_t)(it & 3) * STAGE_B;
        if (it + 3 < nst)
            stage_load(sbase + (uint32_t)((it + 3) & 3) * STAGE_B,
                       m0, start + it + 3, tid);

        #pragma unroll
        for (int ks = 0; ks < 2; ++ks) {
            uint32_t A[4][4], B[3][4];
            #pragma unroll
            for (int mi = 0; mi < 4; ++mi)
                ldm4(A[mi], buf + aoff + mi * (16 * 80) + ks * 32);
            #pragma unroll
            for (int nj = 0; nj < 3; ++nj)
                ldm4(B[nj], buf + boff + nj * (16 * 80) + ks * 32);
            #pragma unroll
            for (int mi = 0; mi < 4; ++mi)
                #pragma unroll
                for (int nj = 0; nj < 3; ++nj)
                    #pragma unroll
                    for (int h = 0; h < 2; ++h)
                        mma_f16(acc[mi][nj * 2 + h], A[mi], &B[nj][h * 2]);
        }
    }

    // epilogue: direct partial store
    float* outp = g_part[sb];
    #pragma unroll
    for (int mi = 0; mi < 4; ++mi) {
        int r0 = m0 + wm * 64 + mi * 16 + (l >> 2);
        #pragma unroll
        for (int n = 0; n < 6; ++n) {
            int col = wn * 48 + n * 8 + (l & 3) * 2;
            float2 v0, v1;
            v0.x = acc[mi][n][0]; v0.y = acc[mi][n][1];
            v1.x = acc[mi][n][2]; v1.y = acc[mi][n][3];
            *reinterpret_cast<float2*>(outp + (size_t)r0 * 192 + col) = v0;
            *reinterpret_cast<float2*>(outp + (size_t)(r0 + 8) * 192 + col) = v1;
        }
    }
}

// ---------------- kernel 3: fused reduce + bias + relu + tiny MLP -----------
#define MROWS 16
extern "C" __global__ void __launch_bounds__(256)
redmlp_kernel(const float* __restrict__ b0,
              const float* __restrict__ W1, const float* __restrict__ b1,
              const float* __restrict__ W2, const float* __restrict__ b2,
              float* __restrict__ out)
{
    __shared__ float sW1[13 * 181];
    __shared__ float sW2[10 * 13];
    __shared__ float sb1[13], sb2[10];
    __shared__ float sc[MROWS][184];
    __shared__ float sh[MROWS][16];

    int tid = threadIdx.x;
    int row0 = blockIdx.x * MROWS;

    for (int i = tid; i < 13 * 181; i += 256) sW1[i] = W1[i];
    if (tid < 130) sW2[tid] = W2[tid];
    if (tid < 13) sb1[tid] = b1[tid];
    if (tid < 10) sb2[tid] = b2[tid];

    // fused split-K reduction + bias + relu
    for (int i = tid; i < MROWS * 192; i += 256) {
        int r = i / 192, c = i % 192;
        size_t idx = (size_t)(row0 + r) * 192 + c;
        float v = (c < 181) ? b0[c] : 0.0f;
        #pragma unroll
        for (int s = 0; s < NSPLIT; ++s) v += g_part[s][idx];
        if (c < 181) sc[r][c] = fmaxf(v, 0.0f);
    }
    __syncthreads();

    if (tid < MROWS * 13) {
        int r = tid / 13, o = tid % 13;
        float v = sb1[o];
        const float* w = sW1 + o * 181;
        #pragma unroll 4
        for (int j = 0; j < 181; ++j) v = fmaf(sc[r][j], w[j], v);
        sh[r][o] = fmaxf(v, 0.0f);
    }
    __syncthreads();

    if (tid < MROWS * 10) {
        int r = tid / 10, o = tid % 10;
        float v = sb2[o];
        #pragma unroll
        for (int i = 0; i < 13; ++i) v = fmaf(sh[r][i], sW2[o * 13 + i], v);
        out[(size_t)(row0 + r) * 10 + o] = v;
    }
}

// ---------------- launcher: wconv forked alongside wavelet ------------------
extern "C" void kernel_launch(void* const* d_in, const int* in_sizes, int n_in,
                              void* d_out, int out_size)
{
    const float* x1 = (const float*)d_in[0];
    const float* W0 = (const float*)d_in[3];
    const float* b0 = (const float*)d_in[4];
    const float* W1 = (const float*)d_in[5];
    const float* b1 = (const float*)d_in[6];
    const float* W2 = (const float*)d_in[7];
    const float* b2 = (const float*)d_in[8];
    float* out = (float*)d_out;

    static int inited = 0;
    static cudaStream_t sW;
    static cudaEvent_t eFork, eWC;
    if (!inited) {
        cudaFuncSetAttribute(gemm_hmma_kernel,
                             cudaFuncAttributeMaxDynamicSharedMemorySize,
                             GEMM_SMEM);
        cudaStreamCreateWithFlags(&sW, cudaStreamNonBlocking);
        cudaEventCreateWithFlags(&eFork, cudaEventDisableTiming);
        cudaEventCreateWithFlags(&eWC,   cudaEventDisableTiming);
        inited = 1;
    }

    // fork: wconv runs concurrently with the wavelet kernel
    cudaEventRecord(eFork, 0);
    cudaStreamWaitEvent(sW, eFork, 0);
    wconv_kernel<<<192 * 32768 / 4 / 256, 256, 0, sW>>>(W0);
    cudaEventRecord(eWC, sW);

    wavelet_kernel<<<2048, WTH>>>(x1);

    // join: gemm needs both g_A (origin stream) and g_W (sW)
    cudaStreamWaitEvent(0, eWC, 0);
    dim3 gg(2048 / 128, NSPLIT);   // 16 x 9 = 144 CTAs (one wave)
    gemm_hmma_kernel<<<gg, 256, GEMM_SMEM>>>();

    redmlp_kernel<<<2048 / MROWS, 256>>>(b0, W1, b1, W2, b2, out);
}

// round 14
// speedup vs baseline: 1.5636x; 1.0145x over previous
#include <cuda_runtime.h>
#include <cuda_fp16.h>
#include <cstdint>

#define WTH 256

// ---------------- filter constants (db4-style reconstruction filters) -------
#define LO0f ( 0.23037781330885523f)
#define LO1f ( 0.7148465705525415f)
#define LO2f ( 0.6308807679295904f)
#define LO3f (-0.02798376941698385f)
#define LO4f (-0.18703481171888114f)
#define LO5f ( 0.030841381835986965f)
#define LO6f ( 0.032883011666982945f)
#define LO7f (-0.010597401784997278f)
#define HI0f (-0.010597401784997278f)
#define HI1f (-0.032883011666982945f)
#define HI2f ( 0.030841381835986965f)
#define HI3f ( 0.18703481171888114f)
#define HI4f (-0.02798376941698385f)
#define HI5f (-0.6308807679295904f)
#define HI6f ( 0.7148465705525415f)
#define HI7f (-0.23037781330885523f)

__constant__ int c_NA[10]  = {4096, 2051, 1029, 518, 262, 134, 70, 38, 22, 14};
__constant__ int c_OFF[9]  = {0, 2051, 3080, 3598, 3860, 3994, 4064, 4102, 4124};

// ---------------- scratch (device globals; no runtime allocation) -----------
#define NSPLIT 18
__device__ __align__(128) __half g_A[2048UL * 32768UL];    // relu(feats), fp16
__device__ __align__(128) __half g_W[192UL * 32768UL];     // W0 padded, fp16
__device__ __align__(128) float  g_part[NSPLIT][2048 * 192];
__device__ unsigned int g_ready[16];                       // per-128-row chunk

// ============================ PTX helpers ====================================
__device__ __forceinline__ uint32_t smem_u32(const void* p) {
    uint32_t a;
    asm("{ .reg .u64 t; cvta.to.shared.u64 t, %1; cvt.u32.u64 %0, t; }"
        : "=r"(a) : "l"(p));
    return a;
}
__device__ __forceinline__ void cp16(uint32_t dst, const void* src) {
    asm volatile("cp.async.cg.shared.global [%0], [%1], 16;"
                 :: "r"(dst), "l"(src) : "memory");
}
__device__ __forceinline__ void cp_commit() {
    asm volatile("cp.async.commit_group;" ::: "memory");
}
template <int N>
__device__ __forceinline__ void cp_wait() {
    asm volatile("cp.async.wait_group %0;" :: "n"(N) : "memory");
}
__device__ __forceinline__ void ldm4(uint32_t* r, uint32_t a) {
    asm volatile("ldmatrix.sync.aligned.m8n8.x4.shared.b16 {%0,%1,%2,%3}, [%4];"
                 : "=r"(r[0]), "=r"(r[1]), "=r"(r[2]), "=r"(r[3]) : "r"(a));
}
__device__ __forceinline__ void mma_f16(float* c, const uint32_t* a,
                                        const uint32_t* b) {
    asm volatile("mma.sync.aligned.m16n8k16.row.col.f32.f16.f16.f32 "
                 "{%0,%1,%2,%3}, {%4,%5,%6,%7}, {%8,%9}, {%0,%1,%2,%3};"
                 : "+f"(c[0]), "+f"(c[1]), "+f"(c[2]), "+f"(c[3])
                 : "r"(a[0]), "r"(a[1]), "r"(a[2]), "r"(a[3]),
                   "r"(b[0]), "r"(b[1]));
}
__device__ __forceinline__ unsigned int ld_acquire(const unsigned int* p) {
    unsigned int v;
    asm volatile("ld.acquire.gpu.u32 %0, [%1];" : "=r"(v) : "l"(p) : "memory");
    return v;
}

// ---------------- DWT stage: src[n] -> ca[m], cd[m] -------------------------
__device__ __forceinline__ void dwt_stage(const float* __restrict__ src, int n,
                                          float* __restrict__ ca,
                                          float* __restrict__ cd, int m)
{
    const float LO[8] = {LO0f, LO1f, LO2f, LO3f, LO4f, LO5f, LO6f, LO7f};
    const float HI[8] = {HI0f, HI1f, HI2f, HI3f, HI4f, HI5f, HI6f, HI7f};
    for (int k = threadIdx.x; k < m; k += WTH) {
        int base = 2 * k;
        float alo = 0.0f, ahi = 0.0f;
        if (base >= 6 && base <= n - 2) {
            const float* p = src + base - 6;
            #pragma unroll
            for (int t = 0; t < 8; ++t) {
                float v = p[t];
                alo = fmaf(v, LO[t], alo);
                ahi = fmaf(v, HI[t], ahi);
            }
        } else {
            #pragma unroll
            for (int t = 0; t < 8; ++t) {
                int idx = base + t;
                int e = (idx < 6) ? (5 - idx)
                                  : ((idx < n + 6) ? (idx - 6) : (2 * n + 5 - idx));
                float v = src[e];
                alo = fmaf(v, LO[t], alo);
                ahi = fmaf(v, HI[t], ahi);
            }
        }
        ca[k] = alo;
        cd[k] = ahi;
    }
}

// ---------------- IDWT stage (intermediate, fp32 smem out) ------------------
template <bool HAS_CA, bool HAS_CD>
__device__ __forceinline__ void idwt_stage(const float* __restrict__ ca,
                                           const float* __restrict__ cd,
                                           int n, float* __restrict__ out)
{
    int half = n - 3;
    for (int u = threadIdx.x; u < half; u += WTH) {
        float ev = 0.0f, od = 0.0f;
        if (HAS_CA) {
            float a0 = ca[u], a1 = ca[u + 1], a2 = ca[u + 2], a3 = ca[u + 3];
            ev = fmaf(a3, LO0f, fmaf(a2, LO2f, fmaf(a1, LO4f, a0 * LO6f)));
            od = fmaf(a3, LO1f, fmaf(a2, LO3f, fmaf(a1, LO5f, a0 * LO7f)));
        }
        if (HAS_CD) {
            float d0 = cd[u], d1 = cd[u + 1], d2 = cd[u + 2], d3 = cd[u + 3];
            ev = fmaf(d3, HI0f, fmaf(d2, HI2f, fmaf(d1, HI4f, fmaf(d0, HI6f, ev))));
            od = fmaf(d3, HI1f, fmaf(d2, HI3f, fmaf(d1, HI5f, fmaf(d0, HI7f, od))));
        }
        float2 o2; o2.x = ev; o2.y = od;
        *reinterpret_cast<float2*>(out + 2 * u) = o2;
    }
}

// ---------------- IDWT final: relu + fp16 store to gmem ---------------------
template <bool HAS_CD>
__device__ __forceinline__ void idwt_final(const float* __restrict__ ca,
                                           const float* __restrict__ cd, int n,
                                           __half* __restrict__ dst)
{
    int half = n - 3;
    for (int u = threadIdx.x; u < half; u += WTH) {
        float a0 = ca[u], a1 = ca[u + 1], a2 = ca[u + 2], a3 = ca[u + 3];
        float ev = fmaf(a3, LO0f, fmaf(a2, LO2f, fmaf(a1, LO4f, a0 * LO6f)));
        float od = fmaf(a3, LO1f, fmaf(a2, LO3f, fmaf(a1, LO5f, a0 * LO7f)));
        if (HAS_CD) {
            float d0 = cd[u], d1 = cd[u + 1], d2 = cd[u + 2], d3 = cd[u + 3];
            ev = fmaf(d3, HI0f, fmaf(d2, HI2f, fmaf(d1, HI4f, fmaf(d0, HI6f, ev))));
            od = fmaf(d3, HI1f, fmaf(d2, HI3f, fmaf(d1, HI5f, fmaf(d0, HI7f, od))));
        }
        ev = fmaxf(ev, 0.0f);
        od = fmaxf(od, 0.0f);
        *reinterpret_cast<__half2*>(dst + 2 * u) = __floats2half2_rn(ev, od);
    }
}

// ---------------- kernel 0: reset chunk-ready counters ----------------------
extern "C" __global__ void zero_kernel()
{
    if (threadIdx.x < 16) g_ready[threadIdx.x] = 0;
}

// ---------------- kernel 1: per-row wavelet features ------------------------
extern "C" __global__ void __launch_bounds__(WTH, 6)
wavelet_kernel(const float* __restrict__ x)
{
    __shared__ __align__(16) float s_cds[4138];
    __shared__ __align__(16) float bufA[2052];
    __shared__ __align__(16) float bufB[2052];

    int row = blockIdx.x;
    const float* xr = x + (size_t)row * 4096;
    __half* hr = g_A + (size_t)row * 32768;

    dwt_stage(xr, 4096, bufA, s_cds + c_OFF[0], c_NA[1]);
    __syncthreads();
    {
        float* a_src = bufA;
        float* a_dst = bufB;
        #pragma unroll 1
        for (int l = 2; l <= 9; ++l) {
            dwt_stage(a_src, c_NA[l - 1], a_dst, s_cds + c_OFF[l - 1], c_NA[l]);
            __syncthreads();
            float* t = a_src; a_src = a_dst; a_dst = t;
        }
    }

    #pragma unroll 1
    for (int level = 2; level <= 9; ++level) {
        float* ping = bufA;
        float* pong = bufB;
        idwt_stage<false, true>(nullptr, s_cds + c_OFF[level - 1], c_NA[level], ping);
        __syncthreads();
        if (level == 2) {
            idwt_final<true>(ping, s_cds + c_OFF[0], c_NA[1], hr);
        } else {
            idwt_stage<true, true>(ping, s_cds + c_OFF[level - 2], c_NA[level - 1], pong);
            __syncthreads();
            { float* t = ping; ping = pong; pong = t; }
            for (int j = level - 3; j >= 1; --j) {
                idwt_stage<true, false>(ping, nullptr, c_NA[j + 1], pong);
                __syncthreads();
                float* t = ping; ping = pong; pong = t;
            }
            idwt_final<false>(ping, nullptr, c_NA[1],
                              hr + (size_t)(level - 2) * 4096);
        }
        __syncthreads();
    }

    // release: this row's features are visible; bump the chunk counter
    __threadfence();
    __syncthreads();
    if (threadIdx.x == 0)
        atomicAdd(&g_ready[row >> 7], 1u);
}

// ---------------- kernel 1b: W0 -> fp16 (padded to 192 rows), vectorized ----
extern "C" __global__ void __launch_bounds__(256)
wconv_kernel(const float* __restrict__ W0)
{
    int i4 = (blockIdx.x * 256 + threadIdx.x) * 4;   // over 192*32768
    int row = i4 >> 15;
    __half2 h01, h23;
    if (row < 181) {
        int col = i4 & 32767;
        float4 v = *reinterpret_cast<const float4*>(
            W0 + (size_t)row * 32768 + col);
        h01 = __floats2half2_rn(v.x, v.y);
        h23 = __floats2half2_rn(v.z, v.w);
    } else {
        h01 = __floats2half2_rn(0.f, 0.f);
        h23 = h01;
    }
    __half2* dst = reinterpret_cast<__half2*>(g_W + i4);
    dst[0] = h01;
    dst[1] = h23;
}

// ---------------- kernel 2: HMMA fp16 split-K GEMM with chunk spin-wait -----
// CTA tile: 128(M) x 192(N) full-N; BK = 32 halves; 3-stage cp.async pipeline.
#define STAGE_B   25600
#define NSTAGE    3
#define GEMM_SMEM (NSTAGE * STAGE_B)
#define KSTEPS_TOT 1024          // 32768 / 32
#define SB_STEPS   57            // ceil(1024/18)

__device__ __forceinline__ void stage_load(uint32_t sbase, int m0, int kstep, int tid)
{
    size_t kb = (size_t)kstep * 64;           // byte offset along k
    #pragma unroll
    for (int j = 0; j < 5; ++j) {             // 1280 16B chunks / 256 threads
        int c = tid + j * 256;
        uint32_t dst;
        const char* src;
        if (c < 512) {                         // A tile: 128 rows x 4 chunks
            int row = c >> 2, kc = c & 3;
            dst = sbase + row * 80 + kc * 16;
            src = (const char*)g_A + ((size_t)(m0 + row) << 16) + kb + kc * 16;
        } else {                               // W tile: 192 rows x 4 chunks
            int rc = c - 512;
            int row = rc >> 2, kc = rc & 3;
            dst = sbase + 10240 + row * 80 + kc * 16;
            src = (const char*)g_W + ((size_t)row << 16) + kb + kc * 16;
        }
        cp16(dst, src);
    }
    cp_commit();
}

extern "C" __global__ void __launch_bounds__(256, 1)
gemm_hmma_kernel()
{
    extern __shared__ __align__(128) char smem[];
    uint32_t sbase = smem_u32(smem);
    int tid = threadIdx.x;
    int wid = tid >> 5;
    int l   = tid & 31;
    int wm  = wid >> 2;     // 0..1 : 64 rows each
    int wn  = wid & 3;      // 0..3 : 48 cols each
    int sb  = blockIdx.x;                 // split-K index (fast dim)
    int mb  = blockIdx.y;                 // m-chunk index (slow dim)
    int m0  = mb * 128;
    int start = sb * SB_STEPS;
    int nst = KSTEPS_TOT - start;
    if (nst > SB_STEPS) nst = SB_STEPS;

    // acquire: wait until this 128-row chunk of g_A is fully produced
    if (tid == 0) {
        while (ld_acquire(&g_ready[mb]) < 128u) __nanosleep(256);
    }
    __syncthreads();

    float acc[4][6][4] = {};

    stage_load(sbase,           m0, start,     tid);
    stage_load(sbase + STAGE_B, m0, start + 1, tid);

    uint32_t aoff = (uint32_t)((wm * 64 + (l & 15)) * 80 + (l >> 4) * 16);
    uint32_t boff = (uint32_t)(10240 +
                    (wn * 48 + (l & 7) + ((l >> 4) & 1) * 8) * 80 +
                    ((l >> 3) & 1) * 16);

    int st = 0;
    #pragma unroll 1
    for (int it = 0; it < nst; ++it) {
        if (it == nst - 1) cp_wait<0>(); else cp_wait<1>();
        __syncthreads();
        uint32_t buf = sbase + (uint32_t)st * STAGE_B;
        if (it + 2 < nst) {
            int st2 = st + 2; if (st2 >= 3) st2 -= 3;
            stage_load(sbase + (uint32_t)st2 * STAGE_B, m0, start + it + 2, tid);
        }

        #pragma unroll
        for (int ks = 0; ks < 2; ++ks) {
            uint32_t A[4][4], B[3][4];
            #pragma unroll
            for (int mi = 0; mi < 4; ++mi)
                ldm4(A[mi], buf + aoff + mi * (16 * 80) + ks * 32);
            #pragma unroll
            for (int nj = 0; nj < 3; ++nj)
                ldm4(B[nj], buf + boff + nj * (16 * 80) + ks * 32);
            #pragma unroll
            for (int mi = 0; mi < 4; ++mi)
                #pragma unroll
                for (int nj = 0; nj < 3; ++nj)
                    #pragma unroll
                    for (int h = 0; h < 2; ++h)
                        mma_f16(acc[mi][nj * 2 + h], A[mi], &B[nj][h * 2]);
        }
        ++st; if (st == 3) st = 0;
    }

    // epilogue: direct partial store
    float* outp = g_part[sb];
    #pragma unroll
    for (int mi = 0; mi < 4; ++mi) {
        int r0 = m0 + wm * 64 + mi * 16 + (l >> 2);
        #pragma unroll
        for (int n = 0; n < 6; ++n) {
            int col = wn * 48 + n * 8 + (l & 3) * 2;
            float2 v0, v1;
            v0.x = acc[mi][n][0]; v0.y = acc[mi][n][1];
            v1.x = acc[mi][n][2]; v1.y = acc[mi][n][3];
            *reinterpret_cast<float2*>(outp + (size_t)r0 * 192 + col) = v0;
            *reinterpret_cast<float2*>(outp + (size_t)(r0 + 8) * 192 + col) = v1;
        }
    }
}

// ---------------- kernel 3: fused reduce + bias + relu + tiny MLP -----------
#define MROWS 8
extern "C" __global__ void __launch_bounds__(256)
redmlp_kernel(const float* __restrict__ b0,
              const float* __restrict__ W1, const float* __restrict__ b1,
              const float* __restrict__ W2, const float* __restrict__ b2,
              float* __restrict__ out)
{
    __shared__ float sW1[13 * 181];
    __shared__ float sW2[10 * 13];
    __shared__ float sb1[13], sb2[10];
    __shared__ float sc[MROWS][184];
    __shared__ float sh[MROWS][16];

    int tid = threadIdx.x;
    int row0 = blockIdx.x * MROWS;

    for (int i = tid; i < 13 * 181; i += 256) sW1[i] = W1[i];
    if (tid < 130) sW2[tid] = W2[tid];
    if (tid < 13) sb1[tid] = b1[tid];
    if (tid < 10) sb2[tid] = b2[tid];

    // fused split-K reduction + bias + relu (float2-vectorized)
    for (int i = tid; i < MROWS * 96; i += 256) {
        int r = i / 96, c2 = i % 96;
        int c = c2 * 2;
        size_t idx = ((size_t)(row0 + r) * 192 + c) / 2;   // in float2 units
        float2 acc;
        acc.x = (c < 181) ? b0[c] : 0.0f;
        acc.y = (c + 1 < 181) ? b0[c + 1] : 0.0f;
        #pragma unroll
        for (int s = 0; s < NSPLIT; ++s) {
            float2 v = reinterpret_cast<const float2*>(g_part[s])[idx];
            acc.x += v.x; acc.y += v.y;
        }
        if (c < 181)     sc[r][c]     = fmaxf(acc.x, 0.0f);
        if (c + 1 < 181) sc[r][c + 1] = fmaxf(acc.y, 0.0f);
    }
    __syncthreads();

    if (tid < MROWS * 13) {
        int r = tid / 13, o = tid % 13;
        float v = sb1[o];
        const float* w = sW1 + o * 181;
        #pragma unroll 4
        for (int j = 0; j < 181; ++j) v = fmaf(sc[r][j], w[j], v);
        sh[r][o] = fmaxf(v, 0.0f);
    }
    __syncthreads();

    if (tid < MROWS * 10) {
        int r = tid / 10, o = tid % 10;
        float v = sb2[o];
        #pragma unroll
        for (int i = 0; i < 13; ++i) v = fmaf(sh[r][i], sW2[o * 13 + i], v);
        out[(size_t)(row0 + r) * 10 + o] = v;
    }
}

// ---------------- launcher: spin-overlapped wavelet + gemm ------------------
extern "C" void kernel_launch(void* const* d_in, const int* in_sizes, int n_in,
                              void* d_out, int out_size)
{
    const float* x1 = (const float*)d_in[0];
    const float* W0 = (const float*)d_in[3];
    const float* b0 = (const float*)d_in[4];
    const float* W1 = (const float*)d_in[5];
    const float* b1 = (const float*)d_in[6];
    const float* W2 = (const float*)d_in[7];
    const float* b2 = (const float*)d_in[8];
    float* out = (float*)d_out;

    static int inited = 0;
    static cudaStream_t sG;
    static cudaEvent_t eFork, eG;
    if (!inited) {
        cudaFuncSetAttribute(gemm_hmma_kernel,
                             cudaFuncAttributeMaxDynamicSharedMemorySize,
                             GEMM_SMEM);
        cudaStreamCreateWithFlags(&sG, cudaStreamNonBlocking);
        cudaEventCreateWithFlags(&eFork, cudaEventDisableTiming);
        cudaEventCreateWithFlags(&eG,    cudaEventDisableTiming);
        inited = 1;
    }

    // reset chunk counters, then fork
    zero_kernel<<<1, 32>>>();
    cudaEventRecord(eFork, 0);
    cudaStreamWaitEvent(sG, eFork, 0);

    // forked stream: wconv then the (spin-waiting) gemm
    wconv_kernel<<<192 * 32768 / 4 / 256, 256, 0, sG>>>(W0);

    // origin stream: monolithic wavelet producing g_A + chunk releases
    wavelet_kernel<<<2048, WTH>>>(x1);

    // launched after wavelet in PROGRAM order (safe even if serialized);
    // overlaps via per-chunk spin-wait on g_ready
    dim3 gg(NSPLIT, 2048 / 128);   // x = split-K (fast), y = m-chunk (slow)
    gemm_hmma_kernel<<<gg, 256, GEMM_SMEM, sG>>>();
    cudaEventRecord(eG, sG);

    // join: redmlp needs all partials
    cudaStreamWaitEvent(0, eG, 0);
    redmlp_kernel<<<2048 / MROWS, 256>>>(b0, W1, b1, W2, b2, out);
}